// round 11
// baseline (speedup 1.0000x reference)
#include <cuda_runtime.h>
#include <cuda_fp16.h>
#include <cstdint>

#define OUTW 128

// ---------------- device scratch ----------------
__device__ __half g_LeftH[256 * 2048];      // gathered span features, fp16
__device__ __half g_W1cT[2048 * 2048];      // combined W1^T: [n][k] fp16
__device__ __half g_Ah[256 * 1024];         // left_i @ W1_top        (fp16)
__device__ __half g_Bh[256 * 1024];         // left_j @ W1_bot + b1   (fp16)
__device__ __half g_W2T[512 * 1024];        // W2^T  [N][K] fp16
__device__ __half g_WoT[128 * 512];         // Wo^T  [N][K] fp16
__device__ __half g_h2[65536ull * 512];     // relu(h1@W2+b2) fp16

// ---------------- helpers ----------------
__device__ __forceinline__ uint32_t smem_u32(const void* p) {
    uint32_t a;
    asm("{ .reg .u64 t; cvta.to.shared.u64 t, %1; cvt.u32.u64 %0, t; }"
        : "=r"(a) : "l"(p));
    return a;
}
__device__ __forceinline__ void cp16(uint32_t s, const void* g) {
    asm volatile("cp.async.cg.shared.global [%0], [%1], 16;" :: "r"(s), "l"(g));
}
#define CP_COMMIT() asm volatile("cp.async.commit_group;" ::: "memory")
#define CP_WAIT0()  asm volatile("cp.async.wait_group 0;" ::: "memory")
#define CP_WAIT1()  asm volatile("cp.async.wait_group 1;" ::: "memory")

__device__ __forceinline__ void ldmx4(uint32_t r[4], uint32_t addr) {
    asm volatile("ldmatrix.sync.aligned.m8n8.x4.shared.b16 {%0,%1,%2,%3}, [%4];"
                 : "=r"(r[0]), "=r"(r[1]), "=r"(r[2]), "=r"(r[3]) : "r"(addr));
}
__device__ __forceinline__ void mma16816(float d[4], const uint32_t a[4],
                                         uint32_t b0, uint32_t b1) {
    asm volatile(
        "mma.sync.aligned.m16n8k16.row.col.f32.f16.f16.f32 "
        "{%0,%1,%2,%3}, {%4,%5,%6,%7}, {%8,%9}, {%0,%1,%2,%3};"
        : "+f"(d[0]), "+f"(d[1]), "+f"(d[2]), "+f"(d[3])
        : "r"(a[0]), "r"(a[1]), "r"(a[2]), "r"(a[3]), "r"(b0), "r"(b1));
}
// swizzled byte offset within a [rows][64 halves] tile (128B rows, 16B chunks)
__device__ __forceinline__ uint32_t tswz(int r, int c) {
    return (uint32_t)(r * 128 + ((c ^ (r & 7)) << 4));
}

// ================================================================
// Kernel 1: merged prep — one launch covers:
//   blocks [0,256):       prep_left   (gather -> g_LeftH)
//   blocks [256,4352):    prep_w1ct   (64x64 tiles -> g_W1cT)
//   blocks [4352,4864):   transpose W2 (16x32 tiles -> g_W2T)
//   blocks [4864,4928):   transpose Wo (4x16 tiles -> g_WoT)
// ================================================================
__global__ __launch_bounds__(256) void prep_all(
    const float* __restrict__ emb, const int* __restrict__ bidx,
    const int* __restrict__ eidx, const float* __restrict__ W1,
    const float* __restrict__ W2, const float* __restrict__ Wo)
{
    __shared__ float t[32][33];
    const int b = blockIdx.x;
    const int tidx = threadIdx.x;

    if (b < 256) {
        // ---- prep_left ----
        const int m = b;
        const int k = tidx * 8;
        const int row = (k < 1024) ? bidx[m] : eidx[m];
        const int col = k & 1023;
        const float4 f0 = *(const float4*)&emb[(size_t)row * 1024 + col];
        const float4 f1 = *(const float4*)&emb[(size_t)row * 1024 + col + 4];
        __half2 h0 = __floats2half2_rn(f0.x, f0.y);
        __half2 h1 = __floats2half2_rn(f0.z, f0.w);
        __half2 h2 = __floats2half2_rn(f1.x, f1.y);
        __half2 h3 = __floats2half2_rn(f1.z, f1.w);
        uint4 o;
        o.x = *(uint32_t*)&h0; o.y = *(uint32_t*)&h1;
        o.z = *(uint32_t*)&h2; o.w = *(uint32_t*)&h3;
        *(uint4*)&g_LeftH[m * 2048 + k] = o;
        return;
    }

    const int x = tidx & 31, y = tidx >> 5;
    if (b < 4352) {
        // ---- prep_w1ct ----
        const int b2 = b - 256;
        const int n0 = (b2 & 63) * 32, k0 = (b2 >> 6) * 32;
        const int srcbase = (n0 < 1024) ? 0 : 2048;
        const int scol0 = n0 & 1023;
#pragma unroll
        for (int dy = 0; dy < 32; dy += 8)
            t[y + dy][x] = W1[(size_t)(srcbase + k0 + y + dy) * 1024 + scol0 + x];
        __syncthreads();
#pragma unroll
        for (int dy = 0; dy < 32; dy += 8)
            g_W1cT[(size_t)(n0 + y + dy) * 2048 + k0 + x] =
                __float2half_rn(t[x][y + dy]);
    } else if (b < 4864) {
        // ---- transpose W2 [1024][512] -> g_W2T [512][1024] ----
        const int b3 = b - 4352;
        const int c0 = (b3 & 15) * 32, r0 = (b3 >> 4) * 32;
#pragma unroll
        for (int dy = 0; dy < 32; dy += 8)
            t[y + dy][x] = W2[(size_t)(r0 + y + dy) * 512 + c0 + x];
        __syncthreads();
#pragma unroll
        for (int dy = 0; dy < 32; dy += 8)
            g_W2T[(size_t)(c0 + y + dy) * 1024 + r0 + x] =
                __float2half_rn(t[x][y + dy]);
    } else {
        // ---- transpose Wo [512][128] -> g_WoT [128][512] ----
        const int b4 = b - 4864;
        const int c0 = (b4 & 3) * 32, r0 = (b4 >> 2) * 32;
#pragma unroll
        for (int dy = 0; dy < 32; dy += 8)
            t[y + dy][x] = Wo[(size_t)(r0 + y + dy) * 128 + c0 + x];
        __syncthreads();
#pragma unroll
        for (int dy = 0; dy < 32; dy += 8)
            g_WoT[(size_t)(c0 + y + dy) * 512 + r0 + x] =
                __float2half_rn(t[x][y + dy]);
    }
}

// ================================================================
// Kernel 2: GEMM1 fp16 — [A|B] = left @ W1c  (proven in R9)
// ================================================================
#define G1_SMEM (3 * 8192 + 3 * 16384)

__global__ __launch_bounds__(256, 1) void gemm1(const float* __restrict__ b1)
{
    extern __shared__ __align__(16) char sm1[];
    char* sA = sm1;             // 3 x 8KB
    char* sB = sm1 + 24576;     // 3 x 16KB
    const uint32_t sAu = smem_u32(sA), sBu = smem_u32(sB);

    const int tid = threadIdx.x, w = tid >> 5, l = tid & 31;
    const int wm = w >> 2, wn = w & 3;
    const int n0 = blockIdx.x * 128, m0 = blockIdx.y * 64;

    float acc[2][4][4];
#pragma unroll
    for (int mt = 0; mt < 2; mt++)
#pragma unroll
        for (int nt = 0; nt < 4; nt++)
#pragma unroll
            for (int q = 0; q < 4; q++) acc[mt][nt][q] = 0.f;

    auto stage = [&](int k0, int s) {
#pragma unroll
        for (int t = 0; t < 2; t++) {
            const int idx = t * 256 + tid;
            const int m = idx >> 3, c = idx & 7;
            cp16(sAu + s * 8192 + tswz(m, c),
                 &g_LeftH[(size_t)(m0 + m) * 2048 + k0 + c * 8]);
        }
#pragma unroll
        for (int t = 0; t < 4; t++) {
            const int idx = t * 256 + tid;
            const int n = idx >> 3, c = idx & 7;
            cp16(sBu + s * 16384 + tswz(n, c),
                 &g_W1cT[(size_t)(n0 + n) * 2048 + k0 + c * 8]);
        }
        CP_COMMIT();
    };

    stage(0, 0);
    stage(64, 1);

    const int lr = l & 15, lc = l >> 4;
    for (int kc = 0; kc < 32; kc++) {
        const int s = kc % 3;
        if (kc < 30) { CP_WAIT1(); } else { CP_WAIT0(); }
        __syncthreads();
        if (kc < 30) stage((kc + 2) * 64, (kc + 2) % 3);

        const uint32_t cAu = sAu + s * 8192;
        const uint32_t cBu = sBu + s * 16384;
#pragma unroll
        for (int ks = 0; ks < 4; ks++) {
            uint32_t a[2][4], b[2][4];
#pragma unroll
            for (int mt = 0; mt < 2; mt++)
                ldmx4(a[mt], cAu + tswz(wm * 32 + mt * 16 + lr, ks * 2 + lc));
#pragma unroll
            for (int nb = 0; nb < 2; nb++)
                ldmx4(b[nb], cBu + tswz(wn * 32 + nb * 16 + lr, ks * 2 + lc));
#pragma unroll
            for (int mt = 0; mt < 2; mt++)
#pragma unroll
                for (int nt = 0; nt < 4; nt++) {
                    const int nb = nt >> 1, hi = nt & 1;
                    mma16816(acc[mt][nt], a[mt], b[nb][hi], b[nb][2 + hi]);
                }
        }
    }

    const int g = l >> 2, tg = l & 3;
#pragma unroll
    for (int mt = 0; mt < 2; mt++) {
        const int r = m0 + wm * 32 + mt * 16 + g;
#pragma unroll
        for (int nt = 0; nt < 4; nt++) {
            const int ng = n0 + wn * 32 + nt * 8 + tg * 2;
            if (ng < 1024) {
                __half2 v0 = __floats2half2_rn(acc[mt][nt][0], acc[mt][nt][1]);
                __half2 v1 = __floats2half2_rn(acc[mt][nt][2], acc[mt][nt][3]);
                *(uint32_t*)&g_Ah[r * 1024 + ng]       = *(uint32_t*)&v0;
                *(uint32_t*)&g_Ah[(r + 8) * 1024 + ng] = *(uint32_t*)&v1;
            } else {
                const int nb2 = ng - 1024;
                const float ba = __ldg(&b1[nb2]);
                const float bb = __ldg(&b1[nb2 + 1]);
                __half2 v0 = __floats2half2_rn(acc[mt][nt][0] + ba, acc[mt][nt][1] + bb);
                __half2 v1 = __floats2half2_rn(acc[mt][nt][2] + ba, acc[mt][nt][3] + bb);
                *(uint32_t*)&g_Bh[r * 1024 + nb2]       = *(uint32_t*)&v0;
                *(uint32_t*)&g_Bh[(r + 8) * 1024 + nb2] = *(uint32_t*)&v1;
            }
        }
    }
}

// ================================================================
// Kernel 3: GEMM2 fp16 — h2 = fp16(relu(h1 @ W2 + b2))
// 512 thr (16 warps, 4m x 4n), warp tile 32x64, CTA tile M=128 N=256.
// K=1024 in 8 chunks of 128, 2-stage pipeline (halved barrier count).
// Stage layout: sA 2 x 32KB (2 sub-tiles of [128][64h]),
//               sB 2 x 64KB (2 sub-tiles of [256][64h]). Total 192KB.
// ================================================================
#define G2_SMEM (2 * 32768 + 2 * 65536)

__global__ __launch_bounds__(512, 1) void gemm2(const float* __restrict__ b2)
{
    extern __shared__ __align__(16) char sm[];
    char* sA = sm;            // 2 x 32KB
    char* sB = sm + 65536;    // 2 x 64KB
    const uint32_t sAu = smem_u32(sA), sBu = smem_u32(sB);

    const int tid = threadIdx.x, w = tid >> 5, l = tid & 31;
    const int wm = w >> 2, wn = w & 3;

    const int rb = blockIdx.x >> 1, nh = blockIdx.x & 1;
    const size_t r0 = (size_t)rb * 128;
    const int i = rb >> 1, j0 = (rb & 1) * 128, nbase = nh * 256;
    const __half* __restrict__ Arow = g_Ah + (size_t)i * 1024;

    float acc[2][8][4];
#pragma unroll
    for (int mt = 0; mt < 2; mt++)
#pragma unroll
        for (int nt = 0; nt < 8; nt++)
#pragma unroll
            for (int q = 0; q < 4; q++) acc[mt][nt][q] = 0.f;

    // h1 build: 128 rows x 16 chunks(16B) = 2048 tasks, 4/thread
    uint4 braw[4];
    auto loadB = [&](int k0) {
#pragma unroll
        for (int t = 0; t < 4; t++) {
            const int idx = t * 512 + tid;
            const int m = idx >> 4, c16 = idx & 15;
            braw[t] = *(const uint4*)&g_Bh[(size_t)(j0 + m) * 1024 + k0 + c16 * 8];
        }
    };
    auto cvtStore = [&](int k0, int s) {
        const __half2 z2 = __floats2half2_rn(0.f, 0.f);
#pragma unroll
        for (int t = 0; t < 4; t++) {
            const int idx = t * 512 + tid;
            const int m = idx >> 4, c16 = idx & 15;
            const int sub = c16 >> 3, c = c16 & 7;
            uint4 araw = *(const uint4*)&Arow[k0 + c16 * 8];   // L1-hot
            const __half2* ah = (const __half2*)&araw;
            const __half2* bh = (const __half2*)&braw[t];
            uint4 o;
            __half2 r0h = __hmax2(__hadd2(ah[0], bh[0]), z2);
            __half2 r1h = __hmax2(__hadd2(ah[1], bh[1]), z2);
            __half2 r2h = __hmax2(__hadd2(ah[2], bh[2]), z2);
            __half2 r3h = __hmax2(__hadd2(ah[3], bh[3]), z2);
            o.x = *(uint32_t*)&r0h; o.y = *(uint32_t*)&r1h;
            o.z = *(uint32_t*)&r2h; o.w = *(uint32_t*)&r3h;
            *(uint4*)(sA + s * 32768 + sub * 16384 + tswz(m, c)) = o;
        }
    };
    // W2 stage: 256 rows x 16 chunks = 4096 tasks, 8/thread
    auto stageB = [&](int k0, int s) {
        const uint32_t dst = sBu + s * 65536;
#pragma unroll
        for (int t = 0; t < 8; t++) {
            const int idx = t * 512 + tid;
            const int n = idx >> 4, c16 = idx & 15;
            const int sub = c16 >> 3, c = c16 & 7;
            cp16(dst + sub * 32768 + tswz(n, c),
                 &g_W2T[(size_t)(nbase + n) * 1024 + k0 + c16 * 8]);
        }
        CP_COMMIT();
    };

    // prologue: stage 0
    stageB(0, 0); loadB(0); cvtStore(0, 0);

    const int lr = l & 15, lc = l >> 4;
    for (int kc = 0; kc < 8; kc++) {
        const int s = kc & 1;
        CP_WAIT0();
        __syncthreads();
        if (kc < 7) { stageB((kc + 1) * 128, s ^ 1); loadB((kc + 1) * 128); }

#pragma unroll
        for (int sub = 0; sub < 2; sub++) {
            const uint32_t cAu = sAu + s * 32768 + sub * 16384;
            const uint32_t cBu = sBu + s * 65536 + sub * 32768;
#pragma unroll
            for (int ks = 0; ks < 4; ks++) {
                uint32_t a[2][4], b[4][4];
#pragma unroll
                for (int mt = 0; mt < 2; mt++) {
                    const int r = wm * 32 + mt * 16 + lr;
                    ldmx4(a[mt], cAu + tswz(r, ks * 2 + lc));
                }
#pragma unroll
                for (int nb = 0; nb < 4; nb++) {
                    const int r = wn * 64 + nb * 16 + lr;
                    ldmx4(b[nb], cBu + tswz(r, ks * 2 + lc));
                }
#pragma unroll
                for (int mt = 0; mt < 2; mt++)
#pragma unroll
                    for (int nt = 0; nt < 8; nt++) {
                        const int nb = nt >> 1, hi = nt & 1;
                        mma16816(acc[mt][nt], a[mt], b[nb][hi], b[nb][2 + hi]);
                    }
            }
        }

        if (kc < 7) cvtStore((kc + 1) * 128, s ^ 1);
    }

    // epilogue: h2 = fp16(relu(acc + b2))
    const int g = l >> 2, tg = l & 3;
#pragma unroll
    for (int mt = 0; mt < 2; mt++) {
        const int r = wm * 32 + mt * 16 + g;
#pragma unroll
        for (int nt = 0; nt < 8; nt++) {
            const int col = nbase + wn * 64 + nt * 8 + tg * 2;
            const float ba = __ldg(&b2[col]);
            const float bb = __ldg(&b2[col + 1]);
            __half2 v0 = __floats2half2_rn(fmaxf(acc[mt][nt][0] + ba, 0.f),
                                           fmaxf(acc[mt][nt][1] + bb, 0.f));
            __half2 v1 = __floats2half2_rn(fmaxf(acc[mt][nt][2] + ba, 0.f),
                                           fmaxf(acc[mt][nt][3] + bb, 0.f));
            *(uint32_t*)&g_h2[(r0 + r) * 512 + col]     = *(uint32_t*)&v0;
            *(uint32_t*)&g_h2[(r0 + r + 8) * 512 + col] = *(uint32_t*)&v1;
        }
    }
}

// ================================================================
// Kernel 4: GEMM3 fp16 — out = h2 @ Wo + bo   [R9, proven]
// 256 thr, tile M=128 N=128, K=512 in 8 chunks of 64, 3-stage.
// ================================================================
#define G3_SMEM (3 * 16384 * 2)

__global__ __launch_bounds__(256, 2) void gemm3(const float* __restrict__ bo,
                                                float* __restrict__ out)
{
    extern __shared__ __align__(16) char sm3[];
    char* sH = sm3;            // 3 x 16KB
    char* sW = sm3 + 49152;    // 3 x 16KB
    const uint32_t sHu = smem_u32(sH), sWu = smem_u32(sW);

    const int tid = threadIdx.x, w = tid >> 5, l = tid & 31;
    const int wm = w >> 1, wn = w & 1;
    const size_t r0 = (size_t)blockIdx.x * 128;

    float acc[2][8][4];
#pragma unroll
    for (int mt = 0; mt < 2; mt++)
#pragma unroll
        for (int nt = 0; nt < 8; nt++)
#pragma unroll
            for (int q = 0; q < 4; q++) acc[mt][nt][q] = 0.f;

    auto stage = [&](int k0, int s) {
        const uint32_t dH = sHu + s * 16384;
        const uint32_t dW = sWu + s * 16384;
#pragma unroll
        for (int t = 0; t < 4; t++) {
            const int idx = t * 256 + tid;
            const int m = idx >> 3, c = idx & 7;
            cp16(dH + tswz(m, c), &g_h2[(r0 + m) * 512 + k0 + c * 8]);
            cp16(dW + tswz(m, c), &g_WoT[(size_t)m * 512 + k0 + c * 8]);
        }
        CP_COMMIT();
    };

    stage(0, 0);
    stage(64, 1);

    const int lr = l & 15, lc = l >> 4;
    for (int kc = 0; kc < 8; kc++) {
        const int s = kc % 3;
        if (kc < 6) { CP_WAIT1(); } else { CP_WAIT0(); }
        __syncthreads();
        if (kc < 6) stage((kc + 2) * 64, (kc + 2) % 3);

        const uint32_t cHu = sHu + s * 16384;
        const uint32_t cWu = sWu + s * 16384;
#pragma unroll
        for (int ks = 0; ks < 4; ks++) {
            uint32_t a[2][4], b[4][4];
#pragma unroll
            for (int mt = 0; mt < 2; mt++) {
                const int r = wm * 32 + mt * 16 + lr;
                ldmx4(a[mt], cHu + tswz(r, ks * 2 + lc));
            }
#pragma unroll
            for (int nb = 0; nb < 4; nb++) {
                const int r = wn * 64 + nb * 16 + lr;
                ldmx4(b[nb], cWu + tswz(r, ks * 2 + lc));
            }
#pragma unroll
            for (int mt = 0; mt < 2; mt++)
#pragma unroll
                for (int nt = 0; nt < 8; nt++) {
                    const int nb = nt >> 1, hi = nt & 1;
                    mma16816(acc[mt][nt], a[mt], b[nb][hi], b[nb][2 + hi]);
                }
        }
    }

    const int g = l >> 2, tg = l & 3;
#pragma unroll
    for (int mt = 0; mt < 2; mt++) {
        const int r = wm * 32 + mt * 16 + g;
#pragma unroll
        for (int nt = 0; nt < 8; nt++) {
            const int col = wn * 64 + nt * 8 + tg * 2;
            const float ba = __ldg(&bo[col]);
            const float bb = __ldg(&bo[col + 1]);
            float2 v0 = make_float2(acc[mt][nt][0] + ba, acc[mt][nt][1] + bb);
            float2 v1 = make_float2(acc[mt][nt][2] + ba, acc[mt][nt][3] + bb);
            *(float2*)&out[(r0 + r) * OUTW + col]     = v0;
            *(float2*)&out[(r0 + r + 8) * OUTW + col] = v1;
        }
    }
}

// ================================================================
extern "C" void kernel_launch(void* const* d_in, const int* in_sizes, int n_in,
                              void* d_out, int out_size) {
    const float* emb  = (const float*)d_in[0];
    const int*   bidx = (const int*)  d_in[1];
    const int*   eidx = (const int*)  d_in[2];
    const float* W1   = (const float*)d_in[3];
    const float* b1   = (const float*)d_in[4];
    const float* W2   = (const float*)d_in[5];
    const float* b2   = (const float*)d_in[6];
    const float* Wo   = (const float*)d_in[7];
    const float* bo   = (const float*)d_in[8];
    float* out = (float*)d_out;

    prep_all<<<4928, 256>>>(emb, bidx, eidx, W1, W2, Wo);

    cudaFuncSetAttribute(gemm1, cudaFuncAttributeMaxDynamicSharedMemorySize, G1_SMEM);
    gemm1<<<dim3(16, 4), 256, G1_SMEM>>>(b1);

    cudaFuncSetAttribute(gemm2, cudaFuncAttributeMaxDynamicSharedMemorySize, G2_SMEM);
    gemm2<<<1024, 512, G2_SMEM>>>(b2);

    cudaFuncSetAttribute(gemm3, cudaFuncAttributeMaxDynamicSharedMemorySize, G3_SMEM);
    gemm3<<<512, 256, G3_SMEM>>>(bo, out);
}

// round 12
// speedup vs baseline: 1.0971x; 1.0971x over previous
#include <cuda_runtime.h>
#include <cuda_fp16.h>
#include <cstdint>

#define OUTW 128

// ---------------- device scratch ----------------
__device__ __half g_LeftH[256 * 2048];      // gathered span features, fp16
__device__ __half g_W1cT[2048 * 2048];      // combined W1^T: [n][k] fp16
__device__ __half g_Ah[256 * 1024];         // left_i @ W1_top        (fp16)
__device__ __half g_Bh[256 * 1024];         // left_j @ W1_bot + b1   (fp16)
__device__ __half g_W2T[512 * 1024];        // W2^T  [N][K] fp16
__device__ __half g_WoT[128 * 512];         // Wo^T  [N][K] fp16
__device__ __half g_h2[65536ull * 512];     // relu(h1@W2+b2) fp16

// ---------------- helpers ----------------
__device__ __forceinline__ uint32_t smem_u32(const void* p) {
    uint32_t a;
    asm("{ .reg .u64 t; cvta.to.shared.u64 t, %1; cvt.u32.u64 %0, t; }"
        : "=r"(a) : "l"(p));
    return a;
}
__device__ __forceinline__ void cp16(uint32_t s, const void* g) {
    asm volatile("cp.async.cg.shared.global [%0], [%1], 16;" :: "r"(s), "l"(g));
}
#define CP_COMMIT() asm volatile("cp.async.commit_group;" ::: "memory")
#define CP_WAIT0()  asm volatile("cp.async.wait_group 0;" ::: "memory")
#define CP_WAIT1()  asm volatile("cp.async.wait_group 1;" ::: "memory")

__device__ __forceinline__ void ldmx4(uint32_t r[4], uint32_t addr) {
    asm volatile("ldmatrix.sync.aligned.m8n8.x4.shared.b16 {%0,%1,%2,%3}, [%4];"
                 : "=r"(r[0]), "=r"(r[1]), "=r"(r[2]), "=r"(r[3]) : "r"(addr));
}
__device__ __forceinline__ void mma16816(float d[4], const uint32_t a[4],
                                         uint32_t b0, uint32_t b1) {
    asm volatile(
        "mma.sync.aligned.m16n8k16.row.col.f32.f16.f16.f32 "
        "{%0,%1,%2,%3}, {%4,%5,%6,%7}, {%8,%9}, {%0,%1,%2,%3};"
        : "+f"(d[0]), "+f"(d[1]), "+f"(d[2]), "+f"(d[3])
        : "r"(a[0]), "r"(a[1]), "r"(a[2]), "r"(a[3]), "r"(b0), "r"(b1));
}
// swizzled byte offset within a [rows][64 halves] tile (128B rows, 16B chunks)
__device__ __forceinline__ uint32_t tswz(int r, int c) {
    return (uint32_t)(r * 128 + ((c ^ (r & 7)) << 4));
}

// ================================================================
// Kernel 1: merged prep — one launch covers:
//   blocks [0,256):       prep_left   (gather -> g_LeftH)
//   blocks [256,4352):    prep_w1ct   (32x32 tiles -> g_W1cT)
//   blocks [4352,4864):   transpose W2 (-> g_W2T)
//   blocks [4864,4928):   transpose Wo (-> g_WoT)
// (verified correct in R11 — rel_err unchanged vs separate kernels)
// ================================================================
__global__ __launch_bounds__(256) void prep_all(
    const float* __restrict__ emb, const int* __restrict__ bidx,
    const int* __restrict__ eidx, const float* __restrict__ W1,
    const float* __restrict__ W2, const float* __restrict__ Wo)
{
    __shared__ float t[32][33];
    const int b = blockIdx.x;
    const int tidx = threadIdx.x;

    if (b < 256) {
        const int m = b;
        const int k = tidx * 8;
        const int row = (k < 1024) ? bidx[m] : eidx[m];
        const int col = k & 1023;
        const float4 f0 = *(const float4*)&emb[(size_t)row * 1024 + col];
        const float4 f1 = *(const float4*)&emb[(size_t)row * 1024 + col + 4];
        __half2 h0 = __floats2half2_rn(f0.x, f0.y);
        __half2 h1 = __floats2half2_rn(f0.z, f0.w);
        __half2 h2 = __floats2half2_rn(f1.x, f1.y);
        __half2 h3 = __floats2half2_rn(f1.z, f1.w);
        uint4 o;
        o.x = *(uint32_t*)&h0; o.y = *(uint32_t*)&h1;
        o.z = *(uint32_t*)&h2; o.w = *(uint32_t*)&h3;
        *(uint4*)&g_LeftH[m * 2048 + k] = o;
        return;
    }

    const int x = tidx & 31, y = tidx >> 5;
    if (b < 4352) {
        const int b2 = b - 256;
        const int n0 = (b2 & 63) * 32, k0 = (b2 >> 6) * 32;
        const int srcbase = (n0 < 1024) ? 0 : 2048;
        const int scol0 = n0 & 1023;
#pragma unroll
        for (int dy = 0; dy < 32; dy += 8)
            t[y + dy][x] = W1[(size_t)(srcbase + k0 + y + dy) * 1024 + scol0 + x];
        __syncthreads();
#pragma unroll
        for (int dy = 0; dy < 32; dy += 8)
            g_W1cT[(size_t)(n0 + y + dy) * 2048 + k0 + x] =
                __float2half_rn(t[x][y + dy]);
    } else if (b < 4864) {
        const int b3 = b - 4352;
        const int c0 = (b3 & 15) * 32, r0 = (b3 >> 4) * 32;
#pragma unroll
        for (int dy = 0; dy < 32; dy += 8)
            t[y + dy][x] = W2[(size_t)(r0 + y + dy) * 512 + c0 + x];
        __syncthreads();
#pragma unroll
        for (int dy = 0; dy < 32; dy += 8)
            g_W2T[(size_t)(c0 + y + dy) * 1024 + r0 + x] =
                __float2half_rn(t[x][y + dy]);
    } else {
        const int b4 = b - 4864;
        const int c0 = (b4 & 3) * 32, r0 = (b4 >> 2) * 32;
#pragma unroll
        for (int dy = 0; dy < 32; dy += 8)
            t[y + dy][x] = Wo[(size_t)(r0 + y + dy) * 128 + c0 + x];
        __syncthreads();
#pragma unroll
        for (int dy = 0; dy < 32; dy += 8)
            g_WoT[(size_t)(c0 + y + dy) * 512 + r0 + x] =
                __float2half_rn(t[x][y + dy]);
    }
}

// ================================================================
// Kernel 2: GEMM1 fp16 — [A|B] = left @ W1c  (proven in R9)
// ================================================================
#define G1_SMEM (3 * 8192 + 3 * 16384)

__global__ __launch_bounds__(256, 1) void gemm1(const float* __restrict__ b1)
{
    extern __shared__ __align__(16) char sm1[];
    char* sA = sm1;             // 3 x 8KB
    char* sB = sm1 + 24576;     // 3 x 16KB
    const uint32_t sAu = smem_u32(sA), sBu = smem_u32(sB);

    const int tid = threadIdx.x, w = tid >> 5, l = tid & 31;
    const int wm = w >> 2, wn = w & 3;
    const int n0 = blockIdx.x * 128, m0 = blockIdx.y * 64;

    float acc[2][4][4];
#pragma unroll
    for (int mt = 0; mt < 2; mt++)
#pragma unroll
        for (int nt = 0; nt < 4; nt++)
#pragma unroll
            for (int q = 0; q < 4; q++) acc[mt][nt][q] = 0.f;

    auto stage = [&](int k0, int s) {
#pragma unroll
        for (int t = 0; t < 2; t++) {
            const int idx = t * 256 + tid;
            const int m = idx >> 3, c = idx & 7;
            cp16(sAu + s * 8192 + tswz(m, c),
                 &g_LeftH[(size_t)(m0 + m) * 2048 + k0 + c * 8]);
        }
#pragma unroll
        for (int t = 0; t < 4; t++) {
            const int idx = t * 256 + tid;
            const int n = idx >> 3, c = idx & 7;
            cp16(sBu + s * 16384 + tswz(n, c),
                 &g_W1cT[(size_t)(n0 + n) * 2048 + k0 + c * 8]);
        }
        CP_COMMIT();
    };

    stage(0, 0);
    stage(64, 1);

    const int lr = l & 15, lc = l >> 4;
    for (int kc = 0; kc < 32; kc++) {
        const int s = kc % 3;
        if (kc < 30) { CP_WAIT1(); } else { CP_WAIT0(); }
        __syncthreads();
        if (kc < 30) stage((kc + 2) * 64, (kc + 2) % 3);

        const uint32_t cAu = sAu + s * 8192;
        const uint32_t cBu = sBu + s * 16384;
#pragma unroll
        for (int ks = 0; ks < 4; ks++) {
            uint32_t a[2][4], b[2][4];
#pragma unroll
            for (int mt = 0; mt < 2; mt++)
                ldmx4(a[mt], cAu + tswz(wm * 32 + mt * 16 + lr, ks * 2 + lc));
#pragma unroll
            for (int nb = 0; nb < 2; nb++)
                ldmx4(b[nb], cBu + tswz(wn * 32 + nb * 16 + lr, ks * 2 + lc));
#pragma unroll
            for (int mt = 0; mt < 2; mt++)
#pragma unroll
                for (int nt = 0; nt < 4; nt++) {
                    const int nb = nt >> 1, hi = nt & 1;
                    mma16816(acc[mt][nt], a[mt], b[nb][hi], b[nb][2 + hi]);
                }
        }
    }

    const int g = l >> 2, tg = l & 3;
#pragma unroll
    for (int mt = 0; mt < 2; mt++) {
        const int r = m0 + wm * 32 + mt * 16 + g;
#pragma unroll
        for (int nt = 0; nt < 4; nt++) {
            const int ng = n0 + wn * 32 + nt * 8 + tg * 2;
            if (ng < 1024) {
                __half2 v0 = __floats2half2_rn(acc[mt][nt][0], acc[mt][nt][1]);
                __half2 v1 = __floats2half2_rn(acc[mt][nt][2], acc[mt][nt][3]);
                *(uint32_t*)&g_Ah[r * 1024 + ng]       = *(uint32_t*)&v0;
                *(uint32_t*)&g_Ah[(r + 8) * 1024 + ng] = *(uint32_t*)&v1;
            } else {
                const int nb2 = ng - 1024;
                const float ba = __ldg(&b1[nb2]);
                const float bb = __ldg(&b1[nb2 + 1]);
                __half2 v0 = __floats2half2_rn(acc[mt][nt][0] + ba, acc[mt][nt][1] + bb);
                __half2 v1 = __floats2half2_rn(acc[mt][nt][2] + ba, acc[mt][nt][3] + bb);
                *(uint32_t*)&g_Bh[r * 1024 + nb2]       = *(uint32_t*)&v0;
                *(uint32_t*)&g_Bh[(r + 8) * 1024 + nb2] = *(uint32_t*)&v1;
            }
        }
    }
}

// ================================================================
// Kernel 3: GEMM2 fp16 — h2 = fp16(relu(h1 @ W2 + b2))   [R9, proven]
// 512 thr (16 warps, 4m x 4n), warp tile 32x64, CTA tile M=128 N=256.
// K=1024 in 16 chunks of 64, 3-stage pipeline.
// ================================================================
#define G2_SMEM (3 * 16384 + 3 * 32768)

__global__ __launch_bounds__(512, 1) void gemm2(const float* __restrict__ b2)
{
    extern __shared__ __align__(16) char sm[];
    char* sA = sm;            // 3 x 16KB
    char* sB = sm + 49152;    // 3 x 32KB
    const uint32_t sAu = smem_u32(sA), sBu = smem_u32(sB);

    const int tid = threadIdx.x, w = tid >> 5, l = tid & 31;
    const int wm = w >> 2, wn = w & 3;

    const int rb = blockIdx.x >> 1, nh = blockIdx.x & 1;
    const size_t r0 = (size_t)rb * 128;
    const int i = rb >> 1, j0 = (rb & 1) * 128, nbase = nh * 256;
    const __half* __restrict__ Arow = g_Ah + (size_t)i * 1024;

    float acc[2][8][4];
#pragma unroll
    for (int mt = 0; mt < 2; mt++)
#pragma unroll
        for (int nt = 0; nt < 8; nt++)
#pragma unroll
            for (int q = 0; q < 4; q++) acc[mt][nt][q] = 0.f;

    uint4 braw[2];
    auto loadB = [&](int k0) {
#pragma unroll
        for (int t = 0; t < 2; t++) {
            const int idx = t * 512 + tid;
            const int m = idx >> 3, c = idx & 7;
            braw[t] = *(const uint4*)&g_Bh[(size_t)(j0 + m) * 1024 + k0 + c * 8];
        }
    };
    auto cvtStore = [&](int k0, int s) {
        const __half2 z2 = __floats2half2_rn(0.f, 0.f);
#pragma unroll
        for (int t = 0; t < 2; t++) {
            const int idx = t * 512 + tid;
            const int m = idx >> 3, c = idx & 7;
            const int kk = k0 + c * 8;
            uint4 araw = *(const uint4*)&Arow[kk];
            const __half2* ah = (const __half2*)&araw;
            const __half2* bh = (const __half2*)&braw[t];
            uint4 o;
            __half2 r0h = __hmax2(__hadd2(ah[0], bh[0]), z2);
            __half2 r1h = __hmax2(__hadd2(ah[1], bh[1]), z2);
            __half2 r2h = __hmax2(__hadd2(ah[2], bh[2]), z2);
            __half2 r3h = __hmax2(__hadd2(ah[3], bh[3]), z2);
            o.x = *(uint32_t*)&r0h; o.y = *(uint32_t*)&r1h;
            o.z = *(uint32_t*)&r2h; o.w = *(uint32_t*)&r3h;
            *(uint4*)(sA + s * 16384 + tswz(m, c)) = o;
        }
    };
    auto stageB = [&](int k0, int s) {
        const uint32_t dst = sBu + s * 32768;
#pragma unroll
        for (int t = 0; t < 4; t++) {
            const int idx = t * 512 + tid;
            const int n = idx >> 3, c = idx & 7;
            cp16(dst + tswz(n, c), &g_W2T[(size_t)(nbase + n) * 1024 + k0 + c * 8]);
        }
        CP_COMMIT();
    };

    stageB(0, 0);  loadB(0);  cvtStore(0, 0);
    stageB(64, 1); loadB(64); cvtStore(64, 1);

    const int lr = l & 15, lc = l >> 4;
    for (int kc = 0; kc < 16; kc++) {
        const int s = kc % 3;
        if (kc < 14) { CP_WAIT1(); } else { CP_WAIT0(); }
        __syncthreads();
        if (kc < 14) { stageB((kc + 2) * 64, (kc + 2) % 3); loadB((kc + 2) * 64); }

        const uint32_t cAu = sAu + s * 16384;
        const uint32_t cBu = sBu + s * 32768;
#pragma unroll
        for (int ks = 0; ks < 4; ks++) {
            uint32_t a[2][4], b[4][4];
#pragma unroll
            for (int mt = 0; mt < 2; mt++) {
                const int r = wm * 32 + mt * 16 + lr;
                ldmx4(a[mt], cAu + tswz(r, ks * 2 + lc));
            }
#pragma unroll
            for (int nb = 0; nb < 4; nb++) {
                const int r = wn * 64 + nb * 16 + lr;
                ldmx4(b[nb], cBu + tswz(r, ks * 2 + lc));
            }
#pragma unroll
            for (int mt = 0; mt < 2; mt++)
#pragma unroll
                for (int nt = 0; nt < 8; nt++) {
                    const int nb = nt >> 1, hi = nt & 1;
                    mma16816(acc[mt][nt], a[mt], b[nb][hi], b[nb][2 + hi]);
                }
        }

        if (kc < 14) cvtStore((kc + 2) * 64, (kc + 2) % 3);
    }

    const int g = l >> 2, tg = l & 3;
#pragma unroll
    for (int mt = 0; mt < 2; mt++) {
        const int r = wm * 32 + mt * 16 + g;
#pragma unroll
        for (int nt = 0; nt < 8; nt++) {
            const int col = nbase + wn * 64 + nt * 8 + tg * 2;
            const float ba = __ldg(&b2[col]);
            const float bb = __ldg(&b2[col + 1]);
            __half2 v0 = __floats2half2_rn(fmaxf(acc[mt][nt][0] + ba, 0.f),
                                           fmaxf(acc[mt][nt][1] + bb, 0.f));
            __half2 v1 = __floats2half2_rn(fmaxf(acc[mt][nt][2] + ba, 0.f),
                                           fmaxf(acc[mt][nt][3] + bb, 0.f));
            *(uint32_t*)&g_h2[(r0 + r) * 512 + col]     = *(uint32_t*)&v0;
            *(uint32_t*)&g_h2[(r0 + r + 8) * 512 + col] = *(uint32_t*)&v1;
        }
    }
}

// ================================================================
// Kernel 4: GEMM3 fp16 — out = h2 @ Wo + bo   [R9, proven]
// 256 thr, tile M=128 N=128, K=512 in 8 chunks of 64, 3-stage.
// ================================================================
#define G3_SMEM (3 * 16384 * 2)

__global__ __launch_bounds__(256, 2) void gemm3(const float* __restrict__ bo,
                                                float* __restrict__ out)
{
    extern __shared__ __align__(16) char sm3[];
    char* sH = sm3;            // 3 x 16KB
    char* sW = sm3 + 49152;    // 3 x 16KB
    const uint32_t sHu = smem_u32(sH), sWu = smem_u32(sW);

    const int tid = threadIdx.x, w = tid >> 5, l = tid & 31;
    const int wm = w >> 1, wn = w & 1;
    const size_t r0 = (size_t)blockIdx.x * 128;

    float acc[2][8][4];
#pragma unroll
    for (int mt = 0; mt < 2; mt++)
#pragma unroll
        for (int nt = 0; nt < 8; nt++)
#pragma unroll
            for (int q = 0; q < 4; q++) acc[mt][nt][q] = 0.f;

    auto stage = [&](int k0, int s) {
        const uint32_t dH = sHu + s * 16384;
        const uint32_t dW = sWu + s * 16384;
#pragma unroll
        for (int t = 0; t < 4; t++) {
            const int idx = t * 256 + tid;
            const int m = idx >> 3, c = idx & 7;
            cp16(dH + tswz(m, c), &g_h2[(r0 + m) * 512 + k0 + c * 8]);
            cp16(dW + tswz(m, c), &g_WoT[(size_t)m * 512 + k0 + c * 8]);
        }
        CP_COMMIT();
    };

    stage(0, 0);
    stage(64, 1);

    const int lr = l & 15, lc = l >> 4;
    for (int kc = 0; kc < 8; kc++) {
        const int s = kc % 3;
        if (kc < 6) { CP_WAIT1(); } else { CP_WAIT0(); }
        __syncthreads();
        if (kc < 6) stage((kc + 2) * 64, (kc + 2) % 3);

        const uint32_t cHu = sHu + s * 16384;
        const uint32_t cWu = sWu + s * 16384;
#pragma unroll
        for (int ks = 0; ks < 4; ks++) {
            uint32_t a[2][4], b[4][4];
#pragma unroll
            for (int mt = 0; mt < 2; mt++) {
                const int r = wm * 32 + mt * 16 + lr;
                ldmx4(a[mt], cHu + tswz(r, ks * 2 + lc));
            }
#pragma unroll
            for (int nb = 0; nb < 4; nb++) {
                const int r = wn * 64 + nb * 16 + lr;
                ldmx4(b[nb], cWu + tswz(r, ks * 2 + lc));
            }
#pragma unroll
            for (int mt = 0; mt < 2; mt++)
#pragma unroll
                for (int nt = 0; nt < 8; nt++) {
                    const int nb = nt >> 1, hi = nt & 1;
                    mma16816(acc[mt][nt], a[mt], b[nb][hi], b[nb][2 + hi]);
                }
        }
    }

    const int g = l >> 2, tg = l & 3;
#pragma unroll
    for (int mt = 0; mt < 2; mt++) {
        const int r = wm * 32 + mt * 16 + g;
#pragma unroll
        for (int nt = 0; nt < 8; nt++) {
            const int col = wn * 64 + nt * 8 + tg * 2;
            const float ba = __ldg(&bo[col]);
            const float bb = __ldg(&bo[col + 1]);
            float2 v0 = make_float2(acc[mt][nt][0] + ba, acc[mt][nt][1] + bb);
            float2 v1 = make_float2(acc[mt][nt][2] + ba, acc[mt][nt][3] + bb);
            *(float2*)&out[(r0 + r) * OUTW + col]     = v0;
            *(float2*)&out[(r0 + r + 8) * OUTW + col] = v1;
        }
    }
}

// ================================================================
extern "C" void kernel_launch(void* const* d_in, const int* in_sizes, int n_in,
                              void* d_out, int out_size) {
    const float* emb  = (const float*)d_in[0];
    const int*   bidx = (const int*)  d_in[1];
    const int*   eidx = (const int*)  d_in[2];
    const float* W1   = (const float*)d_in[3];
    const float* b1   = (const float*)d_in[4];
    const float* W2   = (const float*)d_in[5];
    const float* b2   = (const float*)d_in[6];
    const float* Wo   = (const float*)d_in[7];
    const float* bo   = (const float*)d_in[8];
    float* out = (float*)d_out;

    prep_all<<<4928, 256>>>(emb, bidx, eidx, W1, W2, Wo);

    cudaFuncSetAttribute(gemm1, cudaFuncAttributeMaxDynamicSharedMemorySize, G1_SMEM);
    gemm1<<<dim3(16, 4), 256, G1_SMEM>>>(b1);

    cudaFuncSetAttribute(gemm2, cudaFuncAttributeMaxDynamicSharedMemorySize, G2_SMEM);
    gemm2<<<1024, 512, G2_SMEM>>>(b2);

    cudaFuncSetAttribute(gemm3, cudaFuncAttributeMaxDynamicSharedMemorySize, G3_SMEM);
    gemm3<<<512, 256, G3_SMEM>>>(bo, out);
}

// round 13
// speedup vs baseline: 1.1202x; 1.0211x over previous
#include <cuda_runtime.h>
#include <cuda_fp16.h>
#include <cstdint>

#define OUTW 128

// ---------------- device scratch ----------------
__device__ __half g_LeftH[256 * 2048];      // gathered span features, fp16
__device__ __half g_W1cT[2048 * 2048];      // combined W1^T: [n][k] fp16
__device__ __half g_Ah[256 * 1024];         // left_i @ W1_top        (fp16)
__device__ __half g_Bh[256 * 1024];         // left_j @ W1_bot + b1   (fp16)
__device__ __half g_W2T[512 * 1024];        // W2^T  [N][K] fp16
__device__ __half g_WoT[128 * 512];         // Wo^T  [N][K] fp16
__device__ __half g_h2[65536ull * 512];     // relu(h1@W2+b2) fp16

// ---------------- helpers ----------------
__device__ __forceinline__ uint32_t smem_u32(const void* p) {
    uint32_t a;
    asm("{ .reg .u64 t; cvta.to.shared.u64 t, %1; cvt.u32.u64 %0, t; }"
        : "=r"(a) : "l"(p));
    return a;
}
__device__ __forceinline__ void cp16(uint32_t s, const void* g) {
    asm volatile("cp.async.cg.shared.global [%0], [%1], 16;" :: "r"(s), "l"(g));
}
#define CP_COMMIT() asm volatile("cp.async.commit_group;" ::: "memory")
#define CP_WAIT0()  asm volatile("cp.async.wait_group 0;" ::: "memory")
#define CP_WAIT1()  asm volatile("cp.async.wait_group 1;" ::: "memory")

__device__ __forceinline__ void ldmx4(uint32_t r[4], uint32_t addr) {
    asm volatile("ldmatrix.sync.aligned.m8n8.x4.shared.b16 {%0,%1,%2,%3}, [%4];"
                 : "=r"(r[0]), "=r"(r[1]), "=r"(r[2]), "=r"(r[3]) : "r"(addr));
}
__device__ __forceinline__ void mma16816(float d[4], const uint32_t a[4],
                                         uint32_t b0, uint32_t b1) {
    asm volatile(
        "mma.sync.aligned.m16n8k16.row.col.f32.f16.f16.f32 "
        "{%0,%1,%2,%3}, {%4,%5,%6,%7}, {%8,%9}, {%0,%1,%2,%3};"
        : "+f"(d[0]), "+f"(d[1]), "+f"(d[2]), "+f"(d[3])
        : "r"(a[0]), "r"(a[1]), "r"(a[2]), "r"(a[3]), "r"(b0), "r"(b1));
}
// swizzled byte offset within a [rows][64 halves] tile (128B rows, 16B chunks)
__device__ __forceinline__ uint32_t tswz(int r, int c) {
    return (uint32_t)(r * 128 + ((c ^ (r & 7)) << 4));
}

// ================================================================
// Kernel 1: merged prep (proven R11/R12)
//   blocks [0,256):       prep_left   (gather -> g_LeftH)
//   blocks [256,4352):    prep_w1ct   (32x32 tiles -> g_W1cT)
//   blocks [4352,4864):   transpose W2 (-> g_W2T)
//   blocks [4864,4928):   transpose Wo (-> g_WoT)
// ================================================================
__global__ __launch_bounds__(256) void prep_all(
    const float* __restrict__ emb, const int* __restrict__ bidx,
    const int* __restrict__ eidx, const float* __restrict__ W1,
    const float* __restrict__ W2, const float* __restrict__ Wo)
{
    __shared__ float t[32][33];
    const int b = blockIdx.x;
    const int tidx = threadIdx.x;

    if (b < 256) {
        const int m = b;
        const int k = tidx * 8;
        const int row = (k < 1024) ? bidx[m] : eidx[m];
        const int col = k & 1023;
        const float4 f0 = *(const float4*)&emb[(size_t)row * 1024 + col];
        const float4 f1 = *(const float4*)&emb[(size_t)row * 1024 + col + 4];
        __half2 h0 = __floats2half2_rn(f0.x, f0.y);
        __half2 h1 = __floats2half2_rn(f0.z, f0.w);
        __half2 h2 = __floats2half2_rn(f1.x, f1.y);
        __half2 h3 = __floats2half2_rn(f1.z, f1.w);
        uint4 o;
        o.x = *(uint32_t*)&h0; o.y = *(uint32_t*)&h1;
        o.z = *(uint32_t*)&h2; o.w = *(uint32_t*)&h3;
        *(uint4*)&g_LeftH[m * 2048 + k] = o;
        return;
    }

    const int x = tidx & 31, y = tidx >> 5;
    if (b < 4352) {
        const int b2 = b - 256;
        const int n0 = (b2 & 63) * 32, k0 = (b2 >> 6) * 32;
        const int srcbase = (n0 < 1024) ? 0 : 2048;
        const int scol0 = n0 & 1023;
#pragma unroll
        for (int dy = 0; dy < 32; dy += 8)
            t[y + dy][x] = W1[(size_t)(srcbase + k0 + y + dy) * 1024 + scol0 + x];
        __syncthreads();
#pragma unroll
        for (int dy = 0; dy < 32; dy += 8)
            g_W1cT[(size_t)(n0 + y + dy) * 2048 + k0 + x] =
                __float2half_rn(t[x][y + dy]);
    } else if (b < 4864) {
        const int b3 = b - 4352;
        const int c0 = (b3 & 15) * 32, r0 = (b3 >> 4) * 32;
#pragma unroll
        for (int dy = 0; dy < 32; dy += 8)
            t[y + dy][x] = W2[(size_t)(r0 + y + dy) * 512 + c0 + x];
        __syncthreads();
#pragma unroll
        for (int dy = 0; dy < 32; dy += 8)
            g_W2T[(size_t)(c0 + y + dy) * 1024 + r0 + x] =
                __float2half_rn(t[x][y + dy]);
    } else {
        const int b4 = b - 4864;
        const int c0 = (b4 & 3) * 32, r0 = (b4 >> 2) * 32;
#pragma unroll
        for (int dy = 0; dy < 32; dy += 8)
            t[y + dy][x] = Wo[(size_t)(r0 + y + dy) * 128 + c0 + x];
        __syncthreads();
#pragma unroll
        for (int dy = 0; dy < 32; dy += 8)
            g_WoT[(size_t)(c0 + y + dy) * 512 + r0 + x] =
                __float2half_rn(t[x][y + dy]);
    }
}

// ================================================================
// Kernel 2: GEMM1 fp16 — [A|B] = left @ W1c  (M=256, N=2048, K=2048)
// R13: CTA tile M=64 N=64, grid (32,4) = 128 CTAs (was 64 — half chip idle).
// 256 thr (8 warps 2m x 4n, warp tile 32x16), K in 32 chunks of 64, 3-stage.
// ================================================================
#define G1_SMEM (3 * 8192 + 3 * 8192)

__global__ __launch_bounds__(256, 1) void gemm1(const float* __restrict__ b1)
{
    extern __shared__ __align__(16) char sm1[];
    char* sA = sm1;             // 3 x 8KB
    char* sB = sm1 + 24576;     // 3 x 8KB
    const uint32_t sAu = smem_u32(sA), sBu = smem_u32(sB);

    const int tid = threadIdx.x, w = tid >> 5, l = tid & 31;
    const int wm = w >> 2, wn = w & 3;
    const int n0 = blockIdx.x * 64, m0 = blockIdx.y * 64;

    float acc[2][2][4];
#pragma unroll
    for (int mt = 0; mt < 2; mt++)
#pragma unroll
        for (int nt = 0; nt < 2; nt++)
#pragma unroll
            for (int q = 0; q < 4; q++) acc[mt][nt][q] = 0.f;

    auto stage = [&](int k0, int s) {
#pragma unroll
        for (int t = 0; t < 2; t++) {           // A: 512 tasks
            const int idx = t * 256 + tid;
            const int m = idx >> 3, c = idx & 7;
            cp16(sAu + s * 8192 + tswz(m, c),
                 &g_LeftH[(size_t)(m0 + m) * 2048 + k0 + c * 8]);
        }
#pragma unroll
        for (int t = 0; t < 2; t++) {           // B: 512 tasks
            const int idx = t * 256 + tid;
            const int n = idx >> 3, c = idx & 7;
            cp16(sBu + s * 8192 + tswz(n, c),
                 &g_W1cT[(size_t)(n0 + n) * 2048 + k0 + c * 8]);
        }
        CP_COMMIT();
    };

    stage(0, 0);
    stage(64, 1);

    const int lr = l & 15, lc = l >> 4;
    for (int kc = 0; kc < 32; kc++) {
        const int s = kc % 3;
        if (kc < 30) { CP_WAIT1(); } else { CP_WAIT0(); }
        __syncthreads();
        if (kc < 30) stage((kc + 2) * 64, (kc + 2) % 3);

        const uint32_t cAu = sAu + s * 8192;
        const uint32_t cBu = sBu + s * 8192;
#pragma unroll
        for (int ks = 0; ks < 4; ks++) {
            uint32_t a[2][4], b[4];
#pragma unroll
            for (int mt = 0; mt < 2; mt++)
                ldmx4(a[mt], cAu + tswz(wm * 32 + mt * 16 + lr, ks * 2 + lc));
            ldmx4(b, cBu + tswz(wn * 16 + lr, ks * 2 + lc));
#pragma unroll
            for (int mt = 0; mt < 2; mt++)
#pragma unroll
                for (int nt = 0; nt < 2; nt++)
                    mma16816(acc[mt][nt], a[mt], b[nt], b[2 + nt]);
        }
    }

    const int g = l >> 2, tg = l & 3;
#pragma unroll
    for (int mt = 0; mt < 2; mt++) {
        const int r = m0 + wm * 32 + mt * 16 + g;
#pragma unroll
        for (int nt = 0; nt < 2; nt++) {
            const int ng = n0 + wn * 16 + nt * 8 + tg * 2;
            if (ng < 1024) {
                __half2 v0 = __floats2half2_rn(acc[mt][nt][0], acc[mt][nt][1]);
                __half2 v1 = __floats2half2_rn(acc[mt][nt][2], acc[mt][nt][3]);
                *(uint32_t*)&g_Ah[r * 1024 + ng]       = *(uint32_t*)&v0;
                *(uint32_t*)&g_Ah[(r + 8) * 1024 + ng] = *(uint32_t*)&v1;
            } else {
                const int nb2 = ng - 1024;
                const float ba = __ldg(&b1[nb2]);
                const float bb = __ldg(&b1[nb2 + 1]);
                __half2 v0 = __floats2half2_rn(acc[mt][nt][0] + ba, acc[mt][nt][1] + bb);
                __half2 v1 = __floats2half2_rn(acc[mt][nt][2] + ba, acc[mt][nt][3] + bb);
                *(uint32_t*)&g_Bh[r * 1024 + nb2]       = *(uint32_t*)&v0;
                *(uint32_t*)&g_Bh[(r + 8) * 1024 + nb2] = *(uint32_t*)&v1;
            }
        }
    }
}

// ================================================================
// Kernel 3: GEMM2 fp16 — h2 = fp16(relu(h1 @ W2 + b2))   [R9/R12, proven]
// 512 thr (16 warps, 4m x 4n), warp tile 32x64, CTA tile M=128 N=256.
// K=1024 in 16 chunks of 64, 3-stage pipeline.
// ================================================================
#define G2_SMEM (3 * 16384 + 3 * 32768)

__global__ __launch_bounds__(512, 1) void gemm2(const float* __restrict__ b2)
{
    extern __shared__ __align__(16) char sm[];
    char* sA = sm;            // 3 x 16KB
    char* sB = sm + 49152;    // 3 x 32KB
    const uint32_t sAu = smem_u32(sA), sBu = smem_u32(sB);

    const int tid = threadIdx.x, w = tid >> 5, l = tid & 31;
    const int wm = w >> 2, wn = w & 3;

    const int rb = blockIdx.x >> 1, nh = blockIdx.x & 1;
    const size_t r0 = (size_t)rb * 128;
    const int i = rb >> 1, j0 = (rb & 1) * 128, nbase = nh * 256;
    const __half* __restrict__ Arow = g_Ah + (size_t)i * 1024;

    float acc[2][8][4];
#pragma unroll
    for (int mt = 0; mt < 2; mt++)
#pragma unroll
        for (int nt = 0; nt < 8; nt++)
#pragma unroll
            for (int q = 0; q < 4; q++) acc[mt][nt][q] = 0.f;

    uint4 braw[2];
    auto loadB = [&](int k0) {
#pragma unroll
        for (int t = 0; t < 2; t++) {
            const int idx = t * 512 + tid;
            const int m = idx >> 3, c = idx & 7;
            braw[t] = *(const uint4*)&g_Bh[(size_t)(j0 + m) * 1024 + k0 + c * 8];
        }
    };
    auto cvtStore = [&](int k0, int s) {
        const __half2 z2 = __floats2half2_rn(0.f, 0.f);
#pragma unroll
        for (int t = 0; t < 2; t++) {
            const int idx = t * 512 + tid;
            const int m = idx >> 3, c = idx & 7;
            const int kk = k0 + c * 8;
            uint4 araw = *(const uint4*)&Arow[kk];
            const __half2* ah = (const __half2*)&araw;
            const __half2* bh = (const __half2*)&braw[t];
            uint4 o;
            __half2 r0h = __hmax2(__hadd2(ah[0], bh[0]), z2);
            __half2 r1h = __hmax2(__hadd2(ah[1], bh[1]), z2);
            __half2 r2h = __hmax2(__hadd2(ah[2], bh[2]), z2);
            __half2 r3h = __hmax2(__hadd2(ah[3], bh[3]), z2);
            o.x = *(uint32_t*)&r0h; o.y = *(uint32_t*)&r1h;
            o.z = *(uint32_t*)&r2h; o.w = *(uint32_t*)&r3h;
            *(uint4*)(sA + s * 16384 + tswz(m, c)) = o;
        }
    };
    auto stageB = [&](int k0, int s) {
        const uint32_t dst = sBu + s * 32768;
#pragma unroll
        for (int t = 0; t < 4; t++) {
            const int idx = t * 512 + tid;
            const int n = idx >> 3, c = idx & 7;
            cp16(dst + tswz(n, c), &g_W2T[(size_t)(nbase + n) * 1024 + k0 + c * 8]);
        }
        CP_COMMIT();
    };

    stageB(0, 0);  loadB(0);  cvtStore(0, 0);
    stageB(64, 1); loadB(64); cvtStore(64, 1);

    const int lr = l & 15, lc = l >> 4;
    for (int kc = 0; kc < 16; kc++) {
        const int s = kc % 3;
        if (kc < 14) { CP_WAIT1(); } else { CP_WAIT0(); }
        __syncthreads();
        if (kc < 14) { stageB((kc + 2) * 64, (kc + 2) % 3); loadB((kc + 2) * 64); }

        const uint32_t cAu = sAu + s * 16384;
        const uint32_t cBu = sBu + s * 32768;
#pragma unroll
        for (int ks = 0; ks < 4; ks++) {
            uint32_t a[2][4], b[4][4];
#pragma unroll
            for (int mt = 0; mt < 2; mt++) {
                const int r = wm * 32 + mt * 16 + lr;
                ldmx4(a[mt], cAu + tswz(r, ks * 2 + lc));
            }
#pragma unroll
            for (int nb = 0; nb < 4; nb++) {
                const int r = wn * 64 + nb * 16 + lr;
                ldmx4(b[nb], cBu + tswz(r, ks * 2 + lc));
            }
#pragma unroll
            for (int mt = 0; mt < 2; mt++)
#pragma unroll
                for (int nt = 0; nt < 8; nt++) {
                    const int nb = nt >> 1, hi = nt & 1;
                    mma16816(acc[mt][nt], a[mt], b[nb][hi], b[nb][2 + hi]);
                }
        }

        if (kc < 14) cvtStore((kc + 2) * 64, (kc + 2) % 3);
    }

    const int g = l >> 2, tg = l & 3;
#pragma unroll
    for (int mt = 0; mt < 2; mt++) {
        const int r = wm * 32 + mt * 16 + g;
#pragma unroll
        for (int nt = 0; nt < 8; nt++) {
            const int col = nbase + wn * 64 + nt * 8 + tg * 2;
            const float ba = __ldg(&b2[col]);
            const float bb = __ldg(&b2[col + 1]);
            __half2 v0 = __floats2half2_rn(fmaxf(acc[mt][nt][0] + ba, 0.f),
                                           fmaxf(acc[mt][nt][1] + bb, 0.f));
            __half2 v1 = __floats2half2_rn(fmaxf(acc[mt][nt][2] + ba, 0.f),
                                           fmaxf(acc[mt][nt][3] + bb, 0.f));
            *(uint32_t*)&g_h2[(r0 + r) * 512 + col]     = *(uint32_t*)&v0;
            *(uint32_t*)&g_h2[(r0 + r + 8) * 512 + col] = *(uint32_t*)&v1;
        }
    }
}

// ================================================================
// Kernel 4: GEMM3 fp16 — out = h2 @ Wo + bo   [R9/R12, proven]
// 256 thr, tile M=128 N=128, K=512 in 8 chunks of 64, 3-stage.
// ================================================================
#define G3_SMEM (3 * 16384 * 2)

__global__ __launch_bounds__(256, 2) void gemm3(const float* __restrict__ bo,
                                                float* __restrict__ out)
{
    extern __shared__ __align__(16) char sm3[];
    char* sH = sm3;            // 3 x 16KB
    char* sW = sm3 + 49152;    // 3 x 16KB
    const uint32_t sHu = smem_u32(sH), sWu = smem_u32(sW);

    const int tid = threadIdx.x, w = tid >> 5, l = tid & 31;
    const int wm = w >> 1, wn = w & 1;
    const size_t r0 = (size_t)blockIdx.x * 128;

    float acc[2][8][4];
#pragma unroll
    for (int mt = 0; mt < 2; mt++)
#pragma unroll
        for (int nt = 0; nt < 8; nt++)
#pragma unroll
            for (int q = 0; q < 4; q++) acc[mt][nt][q] = 0.f;

    auto stage = [&](int k0, int s) {
        const uint32_t dH = sHu + s * 16384;
        const uint32_t dW = sWu + s * 16384;
#pragma unroll
        for (int t = 0; t < 4; t++) {
            const int idx = t * 256 + tid;
            const int m = idx >> 3, c = idx & 7;
            cp16(dH + tswz(m, c), &g_h2[(r0 + m) * 512 + k0 + c * 8]);
            cp16(dW + tswz(m, c), &g_WoT[(size_t)m * 512 + k0 + c * 8]);
        }
        CP_COMMIT();
    };

    stage(0, 0);
    stage(64, 1);

    const int lr = l & 15, lc = l >> 4;
    for (int kc = 0; kc < 8; kc++) {
        const int s = kc % 3;
        if (kc < 6) { CP_WAIT1(); } else { CP_WAIT0(); }
        __syncthreads();
        if (kc < 6) stage((kc + 2) * 64, (kc + 2) % 3);

        const uint32_t cHu = sHu + s * 16384;
        const uint32_t cWu = sWu + s * 16384;
#pragma unroll
        for (int ks = 0; ks < 4; ks++) {
            uint32_t a[2][4], b[4][4];
#pragma unroll
            for (int mt = 0; mt < 2; mt++) {
                const int r = wm * 32 + mt * 16 + lr;
                ldmx4(a[mt], cHu + tswz(r, ks * 2 + lc));
            }
#pragma unroll
            for (int nb = 0; nb < 4; nb++) {
                const int r = wn * 64 + nb * 16 + lr;
                ldmx4(b[nb], cWu + tswz(r, ks * 2 + lc));
            }
#pragma unroll
            for (int mt = 0; mt < 2; mt++)
#pragma unroll
                for (int nt = 0; nt < 8; nt++) {
                    const int nb = nt >> 1, hi = nt & 1;
                    mma16816(acc[mt][nt], a[mt], b[nb][hi], b[nb][2 + hi]);
                }
        }
    }

    const int g = l >> 2, tg = l & 3;
#pragma unroll
    for (int mt = 0; mt < 2; mt++) {
        const int r = wm * 32 + mt * 16 + g;
#pragma unroll
        for (int nt = 0; nt < 8; nt++) {
            const int col = wn * 64 + nt * 8 + tg * 2;
            const float ba = __ldg(&bo[col]);
            const float bb = __ldg(&bo[col + 1]);
            float2 v0 = make_float2(acc[mt][nt][0] + ba, acc[mt][nt][1] + bb);
            float2 v1 = make_float2(acc[mt][nt][2] + ba, acc[mt][nt][3] + bb);
            *(float2*)&out[(r0 + r) * OUTW + col]     = v0;
            *(float2*)&out[(r0 + r + 8) * OUTW + col] = v1;
        }
    }
}

// ================================================================
extern "C" void kernel_launch(void* const* d_in, const int* in_sizes, int n_in,
                              void* d_out, int out_size) {
    const float* emb  = (const float*)d_in[0];
    const int*   bidx = (const int*)  d_in[1];
    const int*   eidx = (const int*)  d_in[2];
    const float* W1   = (const float*)d_in[3];
    const float* b1   = (const float*)d_in[4];
    const float* W2   = (const float*)d_in[5];
    const float* b2   = (const float*)d_in[6];
    const float* Wo   = (const float*)d_in[7];
    const float* bo   = (const float*)d_in[8];
    float* out = (float*)d_out;

    prep_all<<<4928, 256>>>(emb, bidx, eidx, W1, W2, Wo);

    cudaFuncSetAttribute(gemm1, cudaFuncAttributeMaxDynamicSharedMemorySize, G1_SMEM);
    gemm1<<<dim3(32, 4), 256, G1_SMEM>>>(b1);

    cudaFuncSetAttribute(gemm2, cudaFuncAttributeMaxDynamicSharedMemorySize, G2_SMEM);
    gemm2<<<1024, 512, G2_SMEM>>>(b2);

    cudaFuncSetAttribute(gemm3, cudaFuncAttributeMaxDynamicSharedMemorySize, G3_SMEM);
    gemm3<<<512, 256, G3_SMEM>>>(bo, out);
}